// round 1
// baseline (speedup 1.0000x reference)
#include <cuda_runtime.h>

// OpticalConvolution: 3x3 conv, pad 1, stride 1.
// B=16, Cin=128, H=W=56, Cout=256. fp32.
//
// Implicit-GEMM style tiled direct conv:
//   grid = (49 spatial tiles of 8x8, Cout/128 = 2, B = 16)
//   block = 128 threads; each thread computes 8 (cout) x 8 (x, one y row).
//   K loop over Cin in chunks of 8; weights staged transposed in smem
//   (stride-129 pad => conflict-free transpose store, broadcast-friendly reads),
//   input 10x10 halo tile staged in smem with stride-12 rows.

#define CIN   128
#define COUT  256
#define HH    56
#define WW    56
#define KC    8          // Cin chunk
#define WS_STRIDE 129    // 128 co + 1 pad

__global__ __launch_bounds__(128)
void optical_conv_kernel(const float* __restrict__ in,
                         const float* __restrict__ wt,
                         const float* __restrict__ bias,
                         float* __restrict__ out)
{
    __shared__ __align__(16) float Ws[72 * WS_STRIDE];   // [r=ci*9+ky*3+kx][co]
    __shared__ __align__(16) float Is[KC * 10 * 12];     // [k][yy (10)][xx (12, 10 used)]

    const int t  = threadIdx.x;
    const int tileId = blockIdx.x;          // 0..48
    const int ty = tileId / 7;
    const int tx = tileId % 7;
    const int y0 = ty * 8;
    const int x0 = tx * 8;
    const int co0 = blockIdx.y * 128;
    const int b   = blockIdx.z;

    const int y  = t & 7;     // this thread's output row within tile
    const int cg = t >> 3;    // cout group (0..15), 8 couts each

    float acc[8][8];
    #pragma unroll
    for (int c = 0; c < 8; c++)
        #pragma unroll
        for (int j = 0; j < 8; j++)
            acc[c][j] = 0.0f;

    const float* wbase = wt + (long)(co0) * (CIN * 9);
    const float* ibase = in + ((long)b * CIN) * (HH * WW);

    for (int ci0 = 0; ci0 < CIN; ci0 += KC) {
        // ---- stage weights chunk: 128 co x 72 (ci_local*9 + ky*3 + kx) ----
        // global: W[co][ci][ky][kx], contiguous 72 floats per co at offset ci0*9.
        for (int i = t; i < 128 * 72; i += 128) {
            int co = i / 72;
            int r  = i - co * 72;
            float v = wbase[(long)co * (CIN * 9) + ci0 * 9 + r];
            Ws[r * WS_STRIDE + co] = v;   // stride 129 => conflict-free
        }

        // ---- stage input halo tile: KC x 10 x 10 (zero-padded borders) ----
        for (int i = t; i < KC * 100; i += 128) {
            int k   = i / 100;
            int rem = i - k * 100;
            int yy  = rem / 10;
            int xx  = rem - yy * 10;
            int iy  = y0 + yy - 1;
            int ix  = x0 + xx - 1;
            float v = 0.0f;
            if (iy >= 0 && iy < HH && ix >= 0 && ix < WW)
                v = ibase[((long)(ci0 + k) * HH + iy) * WW + ix];
            Is[k * 120 + yy * 12 + xx] = v;
        }

        __syncthreads();

        // ---- compute ----
        for (int k = 0; k < KC; k++) {
            #pragma unroll
            for (int ky = 0; ky < 3; ky++) {
                // load 10 input values for row y+ky (vectorized)
                const float* row = &Is[k * 120 + (y + ky) * 12];
                float iv[10];
                {
                    float4 p0 = *(const float4*)(row);
                    float4 p1 = *(const float4*)(row + 4);
                    float2 p2 = *(const float2*)(row + 8);
                    iv[0] = p0.x; iv[1] = p0.y; iv[2] = p0.z; iv[3] = p0.w;
                    iv[4] = p1.x; iv[5] = p1.y; iv[6] = p1.z; iv[7] = p1.w;
                    iv[8] = p2.x; iv[9] = p2.y;
                }
                #pragma unroll
                for (int kx = 0; kx < 3; kx++) {
                    const float* wrow = &Ws[(k * 9 + ky * 3 + kx) * WS_STRIDE + cg * 8];
                    float a[8];
                    #pragma unroll
                    for (int c = 0; c < 8; c++) a[c] = wrow[c];
                    #pragma unroll
                    for (int c = 0; c < 8; c++)
                        #pragma unroll
                        for (int j = 0; j < 8; j++)
                            acc[c][j] = fmaf(a[c], iv[kx + j], acc[c][j]);
                }
            }
        }

        __syncthreads();
    }

    // ---- epilogue: add bias, store 8 co rows x 8 x (two float4 each) ----
    #pragma unroll
    for (int c = 0; c < 8; c++) {
        int co = co0 + cg * 8 + c;
        float bv = __ldg(&bias[co]);
        float* orow = out + (((long)b * COUT + co) * HH + (y0 + y)) * WW + x0;
        float4 v0 = make_float4(acc[c][0] + bv, acc[c][1] + bv,
                                acc[c][2] + bv, acc[c][3] + bv);
        float4 v1 = make_float4(acc[c][4] + bv, acc[c][5] + bv,
                                acc[c][6] + bv, acc[c][7] + bv);
        *(float4*)(orow)     = v0;
        *(float4*)(orow + 4) = v1;
    }
}

extern "C" void kernel_launch(void* const* d_in, const int* in_sizes, int n_in,
                              void* d_out, int out_size)
{
    const float* tensor  = (const float*)d_in[0];   // [16,128,56,56]
    const float* weights = (const float*)d_in[1];   // [256,128,3,3]
    const float* bias    = (const float*)d_in[2];   // [256]
    float* out = (float*)d_out;                     // [16,256,56,56]

    dim3 grid(49, COUT / 128, 16);
    dim3 block(128);
    optical_conv_kernel<<<grid, block>>>(tensor, weights, bias, out);
}

// round 4
// speedup vs baseline: 1.1218x; 1.1218x over previous
#include <cuda_runtime.h>

// OpticalConvolution: 3x3 conv, pad 1, stride 1.
// B=16, Cin=128, H=W=56, Cout=256. fp32.
//
// Round 2/3: packed fp32 math via PTX fma.rn.f32x2 (SASS FFMA2, 2 FMA per
// fma-pipe slot). Accumulators packed along Cout pairs so the weight operand
// comes straight out of smem as LDS.64 (no pack instructions); the input
// operand is a duplicated pair (10 packs per (k,ky), reused across kx/j).

#define CIN   128
#define COUT  256
#define HH    56
#define WW    56
#define KC    8          // Cin chunk
#define WS_STRIDE 130    // 128 co + 2 pad (even => 8B-aligned rows for LDS.64)

typedef unsigned long long u64;

__device__ __forceinline__ u64 pack_dup(float v) {
    u64 r;
    asm("mov.b64 %0, {%1, %1};" : "=l"(r) : "f"(v));
    return r;
}

__device__ __forceinline__ void ffma2(u64& d, u64 a, u64 b) {
    asm("fma.rn.f32x2 %0, %1, %2, %0;" : "+l"(d) : "l"(a), "l"(b));
}

__device__ __forceinline__ void unpack2(u64 v, float& lo, float& hi) {
    asm("mov.b64 {%0, %1}, %2;" : "=f"(lo), "=f"(hi) : "l"(v));
}

__global__ __launch_bounds__(128)
void optical_conv_kernel(const float* __restrict__ in,
                         const float* __restrict__ wt,
                         const float* __restrict__ bias,
                         float* __restrict__ out)
{
    __shared__ __align__(16) float Ws[72 * WS_STRIDE];   // [r=ci*9+ky*3+kx][co]
    __shared__ __align__(16) float Is[KC * 10 * 12];     // [k][yy (10)][xx (12, 10 used)]

    const int t  = threadIdx.x;
    const int tileId = blockIdx.x;          // 0..48
    const int ty = tileId / 7;
    const int tx = tileId % 7;
    const int y0 = ty * 8;
    const int x0 = tx * 8;
    const int co0 = blockIdx.y * 128;
    const int b   = blockIdx.z;

    const int y  = t & 7;     // this thread's output row within tile
    const int cg = t >> 3;    // cout group (0..15), 8 couts each

    // acc pairs: p = cout-pair index (co = cg*8 + 2p, 2p+1), j = x offset
    u64 accp[4][8];
    #pragma unroll
    for (int p = 0; p < 4; p++)
        #pragma unroll
        for (int j = 0; j < 8; j++)
            accp[p][j] = 0ull;

    const float* wbase = wt + (long)(co0) * (CIN * 9);
    const float* ibase = in + ((long)b * CIN) * (HH * WW);

    for (int ci0 = 0; ci0 < CIN; ci0 += KC) {
        // ---- stage weights chunk: 128 co x 72 (ci_local*9 + ky*3 + kx) ----
        for (int i = t; i < 128 * 72; i += 128) {
            int co = i / 72;
            int r  = i - co * 72;
            float v = wbase[(long)co * (CIN * 9) + ci0 * 9 + r];
            Ws[r * WS_STRIDE + co] = v;
        }

        // ---- stage input halo tile: KC x 10 x 10 (zero-padded borders) ----
        for (int i = t; i < KC * 100; i += 128) {
            int k   = i / 100;
            int rem = i - k * 100;
            int yy  = rem / 10;
            int xx  = rem - yy * 10;
            int iy  = y0 + yy - 1;
            int ix  = x0 + xx - 1;
            float v = 0.0f;
            if (iy >= 0 && iy < HH && ix >= 0 && ix < WW)
                v = ibase[((long)(ci0 + k) * HH + iy) * WW + ix];
            Is[k * 120 + yy * 12 + xx] = v;
        }

        __syncthreads();

        // ---- compute ----
        for (int k = 0; k < KC; k++) {
            #pragma unroll
            for (int ky = 0; ky < 3; ky++) {
                const float* row = &Is[k * 120 + (y + ky) * 12];
                u64 ivp[10];
                {
                    float4 p0 = *(const float4*)(row);
                    float4 p1 = *(const float4*)(row + 4);
                    float2 p2 = *(const float2*)(row + 8);
                    ivp[0] = pack_dup(p0.x); ivp[1] = pack_dup(p0.y);
                    ivp[2] = pack_dup(p0.z); ivp[3] = pack_dup(p0.w);
                    ivp[4] = pack_dup(p1.x); ivp[5] = pack_dup(p1.y);
                    ivp[6] = pack_dup(p1.z); ivp[7] = pack_dup(p1.w);
                    ivp[8] = pack_dup(p2.x); ivp[9] = pack_dup(p2.y);
                }
                #pragma unroll
                for (int kx = 0; kx < 3; kx++) {
                    const u64* wrow = (const u64*)&Ws[(k * 9 + ky * 3 + kx) * WS_STRIDE + cg * 8];
                    u64 wp[4];
                    #pragma unroll
                    for (int p = 0; p < 4; p++) wp[p] = wrow[p];   // LDS.64 pairs
                    #pragma unroll
                    for (int p = 0; p < 4; p++)
                        #pragma unroll
                        for (int j = 0; j < 8; j++)
                            ffma2(accp[p][j], wp[p], ivp[kx + j]);
                }
            }
        }

        __syncthreads();
    }

    // ---- epilogue: unpack, add bias, store ----
    #pragma unroll
    for (int p = 0; p < 4; p++) {
        int coA = co0 + cg * 8 + 2 * p;
        int coB = coA + 1;
        float bA = __ldg(&bias[coA]);
        float bB = __ldg(&bias[coB]);
        float a[8], bb[8];
        #pragma unroll
        for (int j = 0; j < 8; j++) {
            float lo, hi;
            unpack2(accp[p][j], lo, hi);
            a[j]  = lo + bA;
            bb[j] = hi + bB;
        }
        float* orowA = out + (((long)b * COUT + coA) * HH + (y0 + y)) * WW + x0;
        float* orowB = out + (((long)b * COUT + coB) * HH + (y0 + y)) * WW + x0;
        *(float4*)(orowA)     = make_float4(a[0], a[1], a[2], a[3]);
        *(float4*)(orowA + 4) = make_float4(a[4], a[5], a[6], a[7]);
        *(float4*)(orowB)     = make_float4(bb[0], bb[1], bb[2], bb[3]);
        *(float4*)(orowB + 4) = make_float4(bb[4], bb[5], bb[6], bb[7]);
    }
}

extern "C" void kernel_launch(void* const* d_in, const int* in_sizes, int n_in,
                              void* d_out, int out_size)
{
    const float* tensor  = (const float*)d_in[0];   // [16,128,56,56]
    const float* weights = (const float*)d_in[1];   // [256,128,3,3]
    const float* bias    = (const float*)d_in[2];   // [256]
    float* out = (float*)d_out;                     // [16,256,56,56]

    dim3 grid(49, COUT / 128, 16);
    dim3 block(128);
    optical_conv_kernel<<<grid, block>>>(tensor, weights, bias, out);
}

// round 6
// speedup vs baseline: 1.7277x; 1.5401x over previous
#include <cuda_runtime.h>
#include <cuda_bf16.h>
#include <stdint.h>

// OpticalConvolution: 3x3 conv pad1 stride1, B=16 Cin=128 H=W=56 Cout=256, fp32.
//
// Round 6: bf16-split implicit GEMM on tensor cores via mma.sync (HMMA),
// since tcgen05 PTX is rejected by the harness's compute_103 target.
//   fp32 x = hi + lo  (hi = truncate-to-bf16, lo = rn(x - hi))
//   D(fp32) += Ahi*Bhi + Ahi*Blo + Alo*Bhi     (lo*lo ~ 2^-16, dropped)
// Block: M=128 couts x N=128 (2 batches x 8x8 spatial), K=1152, 18 stages of 64.
// 8 warps in 2(M) x 4(N); warp tile 64x32; mma.sync.m16n8k16.row.col bf16.

#define CIN   128
#define COUT  256
#define HH    56
#define WW    56
#define KTOT  1152
#define KSTAGE 64
#define NSTAGES 18

// per-stage smem: 4 regions of 128 rows x 64 bf16 (128B rows, SW128-swizzled)
#define REG_SZ 16384
#define A_HI 0
#define A_LO (REG_SZ)
#define B_HI (2 * REG_SZ)
#define B_LO (3 * REG_SZ)
#define BUFSZ (4 * REG_SZ)
#define SMEM_TOTAL (2 * BUFSZ)

#define SWZ(x) ((x) ^ (((x) >> 3) & 0x70))

__device__ __forceinline__ uint32_t lds_swz(const char* base, uint32_t off) {
    return *(const uint32_t*)(base + SWZ(off));
}

// split fp32 pair into (hi: truncated-bf16 pair, lo: rn(residual) pair), k-even in low half
__device__ __forceinline__ void split_pair(float v0, float v1, uint32_t& hi, uint32_t& lo) {
    uint32_t u0 = __float_as_uint(v0), u1 = __float_as_uint(v1);
    asm("prmt.b32 %0, %1, %2, 0x7632;" : "=r"(hi) : "r"(u0), "r"(u1));
    float l0 = v0 - __uint_as_float(u0 & 0xFFFF0000u);
    float l1 = v1 - __uint_as_float(u1 & 0xFFFF0000u);
    asm("cvt.rn.bf16x2.f32 %0, %1, %2;" : "=r"(lo) : "f"(l1), "f"(l0));
}

__device__ __forceinline__ void mma_bf16(float* d, const uint32_t* a, const uint32_t* b) {
    asm volatile(
        "mma.sync.aligned.m16n8k16.row.col.f32.bf16.bf16.f32 "
        "{%0,%1,%2,%3}, {%4,%5,%6,%7}, {%8,%9}, {%0,%1,%2,%3};"
        : "+f"(d[0]), "+f"(d[1]), "+f"(d[2]), "+f"(d[3])
        : "r"(a[0]), "r"(a[1]), "r"(a[2]), "r"(a[3]), "r"(b[0]), "r"(b[1]));
}

__global__ __launch_bounds__(256, 1)
void optical_conv_mma(const float* __restrict__ in,
                      const float* __restrict__ wt,
                      const float* __restrict__ bias,
                      float* __restrict__ out)
{
    extern __shared__ __align__(1024) char smem[];
    const int t = threadIdx.x;
    const int wid = t >> 5;
    const int lane = t & 31;

    const int tileId = blockIdx.x;          // 0..48
    const int ty = tileId / 7, tx = tileId % 7;
    const int y0 = ty * 8, x0 = tx * 8;
    const int co0 = blockIdx.y * 128;
    const int bz = blockIdx.z;              // batches bz*2, bz*2+1

    // ---- per-thread B-staging constants ----
    const int nB = t & 127;                 // B-tile row (n)
    const int hB = t >> 7;                  // which half of the 32 k-pairs
    const int b2 = nB >> 6;
    const int yy = (nB & 63) >> 3, xx = nB & 7;
    const int jxor = yy & 3;                // STS bank-conflict-avoidance permutation
    const float* ib = in + (size_t)(bz * 2 + b2) * (CIN * HH * WW);
    const int oy = y0 + yy - 1, ox = x0 + xx - 1;
    const uint32_t rowByteB = (uint32_t)nB * 128;

    // ---- warp tiling: 2 (M) x 4 (N) warps; warp tile 64 (M) x 32 (N) ----
    const int mrow = (wid & 1) * 64;
    const int ncol = (wid >> 1) * 32;
    const int g = lane >> 2;                // fragment row group
    const int c = lane & 3;                 // fragment k/col group

    float acc[4][4][4];                     // [mt][nt][frag]
    #pragma unroll
    for (int mt = 0; mt < 4; mt++)
        #pragma unroll
        for (int nt = 0; nt < 4; nt++)
            #pragma unroll
            for (int r = 0; r < 4; r++) acc[mt][nt][r] = 0.0f;

    // ---------------- staging lambda (stage s into buffer buf) ----------------
    auto stage = [&](int s, char* buf) {
        // A (weights): warp <-> row group, lane <-> k-pair; coalesced LDG.64
        const float* srcBase = wt + (size_t)co0 * KTOT + s * KSTAGE + 2 * lane;
        #pragma unroll 4
        for (int it = 0; it < 16; it++) {
            int row = it * 8 + wid;
            float2 v = *(const float2*)(srcBase + (size_t)row * KTOT);
            uint32_t hi, lo;
            split_pair(v.x, v.y, hi, lo);
            uint32_t off = SWZ((uint32_t)row * 128 + lane * 4);
            *(uint32_t*)(buf + A_HI + off) = hi;
            *(uint32_t*)(buf + A_LO + off) = lo;
        }
        // B (im2col): thread <-> n row; 16 k-pairs each; slot j = p ^ jxor
        #pragma unroll 4
        for (int jj = 0; jj < 16; jj++) {
            int p = hB * 16 + jj;
            int j = p ^ jxor;
            int k0 = s * KSTAGE + 2 * j;
            int ci = k0 / 9;
            int r  = k0 - ci * 9;
            int ky = (r >= 6) ? 2 : (r >= 3 ? 1 : 0);
            int kx = r - ky * 3;
            int iy = oy + ky, ix = ox + kx;
            float v0 = 0.0f;
            if ((unsigned)iy < HH && (unsigned)ix < WW)
                v0 = ib[(ci * HH + iy) * WW + ix];
            int r1 = r + 1, ci1 = ci;
            if (r1 == 9) { r1 = 0; ci1 = ci + 1; }
            int ky1 = (r1 >= 6) ? 2 : (r1 >= 3 ? 1 : 0);
            int kx1 = r1 - ky1 * 3;
            int iy1 = oy + ky1, ix1 = ox + kx1;
            float v1 = 0.0f;
            if ((unsigned)iy1 < HH && (unsigned)ix1 < WW)
                v1 = ib[(ci1 * HH + iy1) * WW + ix1];
            uint32_t hi, lo;
            split_pair(v0, v1, hi, lo);
            uint32_t off = SWZ(rowByteB + (uint32_t)j * 4);
            *(uint32_t*)(buf + B_HI + off) = hi;
            *(uint32_t*)(buf + B_LO + off) = lo;
        }
    };

    // ---------------- main loop: double-buffered ----------------
    stage(0, smem);
    __syncthreads();

    for (int s = 0; s < NSTAGES; s++) {
        char* cur = smem + (size_t)(s & 1) * BUFSZ;
        if (s + 1 < NSTAGES)
            stage(s + 1, smem + (size_t)((s + 1) & 1) * BUFSZ);

        // compute 4 k16-steps from cur
        #pragma unroll
        for (int q = 0; q < 4; q++) {
            const uint32_t kb = q * 32 + c * 4;
            uint32_t bh[4][2], bl[4][2];
            #pragma unroll
            for (int nt = 0; nt < 4; nt++) {
                uint32_t rB = (uint32_t)(ncol + nt * 8 + g) * 128;
                bh[nt][0] = lds_swz(cur + B_HI, rB + kb);
                bh[nt][1] = lds_swz(cur + B_HI, rB + kb + 16);
                bl[nt][0] = lds_swz(cur + B_LO, rB + kb);
                bl[nt][1] = lds_swz(cur + B_LO, rB + kb + 16);
            }
            #pragma unroll
            for (int mt = 0; mt < 4; mt++) {
                uint32_t rA  = (uint32_t)(mrow + mt * 16 + g) * 128;
                uint32_t rA8 = rA + 8 * 128;
                uint32_t ah[4], al[4];
                ah[0] = lds_swz(cur + A_HI, rA  + kb);
                ah[1] = lds_swz(cur + A_HI, rA8 + kb);
                ah[2] = lds_swz(cur + A_HI, rA  + kb + 16);
                ah[3] = lds_swz(cur + A_HI, rA8 + kb + 16);
                al[0] = lds_swz(cur + A_LO, rA  + kb);
                al[1] = lds_swz(cur + A_LO, rA8 + kb);
                al[2] = lds_swz(cur + A_LO, rA  + kb + 16);
                al[3] = lds_swz(cur + A_LO, rA8 + kb + 16);
                #pragma unroll
                for (int nt = 0; nt < 4; nt++) {
                    mma_bf16(acc[mt][nt], ah, bh[nt]);
                    mma_bf16(acc[mt][nt], ah, bl[nt]);
                    mma_bf16(acc[mt][nt], al, bh[nt]);
                }
            }
        }
        __syncthreads();
    }

    // ---------------- epilogue: bias + direct float2 global stores ----------------
    #pragma unroll
    for (int mt = 0; mt < 4; mt++) {
        int coA = co0 + mrow + mt * 16 + g;
        int coB = coA + 8;
        float bvA = __ldg(&bias[coA]);
        float bvB = __ldg(&bias[coB]);
        #pragma unroll
        for (int nt = 0; nt < 4; nt++) {
            int n0 = ncol + nt * 8 + c * 2;
            int bb = bz * 2 + (n0 >> 6);
            int yq = (n0 >> 3) & 7;
            int xq = n0 & 7;
            float* gA = out + (((size_t)bb * COUT + coA) * HH + (y0 + yq)) * WW + x0 + xq;
            float* gB = out + (((size_t)bb * COUT + coB) * HH + (y0 + yq)) * WW + x0 + xq;
            *(float2*)gA = make_float2(acc[mt][nt][0] + bvA, acc[mt][nt][1] + bvA);
            *(float2*)gB = make_float2(acc[mt][nt][2] + bvB, acc[mt][nt][3] + bvB);
        }
    }
}

extern "C" void kernel_launch(void* const* d_in, const int* in_sizes, int n_in,
                              void* d_out, int out_size)
{
    const float* tensor  = (const float*)d_in[0];   // [16,128,56,56]
    const float* weights = (const float*)d_in[1];   // [256,128,3,3]
    const float* bias    = (const float*)d_in[2];   // [256]
    float* out = (float*)d_out;                     // [16,256,56,56]

    cudaFuncSetAttribute(optical_conv_mma,
                         cudaFuncAttributeMaxDynamicSharedMemorySize, SMEM_TOTAL);
    dim3 grid(49, 2, 8);
    dim3 block(256);
    optical_conv_mma<<<grid, block, SMEM_TOTAL>>>(tensor, weights, bias, out);
}